// round 1
// baseline (speedup 1.0000x reference)
#include <cuda_runtime.h>

// SWAttention AV: out[b,h,n,d] = sum_k (sum_d' q[b,h,n,d']*lt[h,d',k] + bias[h,n,k] + local[b,h,n,k]) * v[b,h,n,d,k]
// B=8, H=8, N=3136, D=32, K2=9. Warp-per-row, lane = d.

#define BB 8
#define HH 8
#define NN 3136
#define DD 32
#define KK 9
#define NROWS (BB * HH * NN)          // 200704
#define WARPS_PER_BLOCK 8

__global__ __launch_bounds__(WARPS_PER_BLOCK * 32)
void swattn_av_kernel(const float* __restrict__ q,
                      const float* __restrict__ attn_local,
                      const float* __restrict__ v,
                      const float* __restrict__ lt,
                      const float* __restrict__ bias,
                      float* __restrict__ out) {
    __shared__ float sv[WARPS_PER_BLOCK][DD * KK];   // 8 * 288 floats = 9216 B

    const int warp = threadIdx.x >> 5;
    const int lane = threadIdx.x & 31;

    const long long R = (long long)blockIdx.x * WARPS_PER_BLOCK + warp;
    if (R >= NROWS) return;

    // ---- Stage 1: issue v row loads early (coalesced float4, 72 float4 per row) ----
    const float4* __restrict__ v4 = reinterpret_cast<const float4*>(v + R * (DD * KK));
    float4 r0 = v4[lane];
    float4 r1 = v4[lane + 32];
    float4 r2 = make_float4(0.f, 0.f, 0.f, 0.f);
    if (lane < 8) r2 = v4[lane + 64];

    // ---- Stage 2: compute attn[k] while v loads are in flight ----
    const float qv = q[R * DD + lane];

    const int hn = (int)(R % (HH * NN));     // h*N + n
    const int h  = hn / NN;

    // lt layout [H, D, K2]; lane = d
    const float* __restrict__ ltp = lt + (h * DD + lane) * KK;
    float a[KK];
    #pragma unroll
    for (int k = 0; k < KK; k++) a[k] = qv * ltp[k];

    // 9 simultaneous butterfly reductions over d
    #pragma unroll
    for (int off = 16; off > 0; off >>= 1) {
        #pragma unroll
        for (int k = 0; k < KK; k++)
            a[k] += __shfl_xor_sync(0xffffffffu, a[k], off);
    }

    // bias[h,n,k] + local[b,h,n,k] (warp-uniform broadcast loads)
    const float* __restrict__ bp = bias + (long long)hn * KK;
    const float* __restrict__ lp = attn_local + R * KK;
    #pragma unroll
    for (int k = 0; k < KK; k++) a[k] += bp[k] + lp[k];

    // ---- Stage 3: park v in shared, conflict-free readback ----
    float4* s4 = reinterpret_cast<float4*>(sv[warp]);
    s4[lane]      = r0;
    s4[lane + 32] = r1;
    if (lane < 8) s4[lane + 64] = r2;
    __syncwarp();

    // out[d=lane] = sum_k a[k] * v[lane, k]; addresses lane*9+k hit distinct banks (gcd(9,32)=1)
    const float* __restrict__ srow = sv[warp] + lane * KK;
    float acc = 0.f;
    #pragma unroll
    for (int k = 0; k < KK; k++) acc = fmaf(a[k], srow[k], acc);

    out[R * DD + lane] = acc;
}

extern "C" void kernel_launch(void* const* d_in, const int* in_sizes, int n_in,
                              void* d_out, int out_size) {
    const float* q          = (const float*)d_in[0];  // [B,H,N,D]
    const float* attn_local = (const float*)d_in[1];  // [B,H,N,K2]
    const float* v_local    = (const float*)d_in[2];  // [B,H,N,D,K2]
    const float* lt         = (const float*)d_in[3];  // [H,D,K2]
    const float* bias       = (const float*)d_in[4];  // [H,N,K2]
    float* out = (float*)d_out;                       // [B,H,N,D]

    const int blocks = (NROWS + WARPS_PER_BLOCK - 1) / WARPS_PER_BLOCK;  // 25088
    swattn_av_kernel<<<blocks, WARPS_PER_BLOCK * 32>>>(q, attn_local, v_local, lt, bias, out);
}

// round 2
// speedup vs baseline: 1.1155x; 1.1155x over previous
#include <cuda_runtime.h>

// SWAttention AV: out[b,h,n,d] = sum_k (sum_d' q[d']*lt[h,d',k] + bias[h,n,k] + local[b,h,n,k]) * v[b,h,n,d,k]
// B=8, H=8, N=3136, D=32, K2=9. Warp-per-row, lane = d.
// R2: lt staged in shared per block (kills 36B-strided LDGs = 81 L1 wavefronts/warp),
//     bias+local loaded by lanes 0-8 and shuffle-broadcast, streaming cache hints on v/q/local.

#define BB 8
#define HH 8
#define NN 3136
#define DD 32
#define KK 9
#define NROWS (BB * HH * NN)          // 200704
#define WARPS_PER_BLOCK 8
#define ROWS_PER_BLOCK WARPS_PER_BLOCK

__global__ __launch_bounds__(WARPS_PER_BLOCK * 32)
void swattn_av_kernel(const float* __restrict__ q,
                      const float* __restrict__ attn_local,
                      const float* __restrict__ v,
                      const float* __restrict__ lt,
                      const float* __restrict__ bias,
                      float* __restrict__ out) {
    __shared__ float sv[WARPS_PER_BLOCK][DD * KK];   // 9216 B
    __shared__ float s_lt[DD * KK];                   // 1152 B, one head per block

    const int tid  = threadIdx.x;
    const int warp = tid >> 5;
    const int lane = tid & 31;

    const long long R0 = (long long)blockIdx.x * ROWS_PER_BLOCK;
    const long long R  = R0 + warp;

    // ---- Issue this warp's v row loads first (coalesced float4, streaming) ----
    const float4* __restrict__ v4 = reinterpret_cast<const float4*>(v + R * (DD * KK));
    float4 r0 = __ldcs(v4 + lane);
    float4 r1 = __ldcs(v4 + lane + 32);
    float4 r2 = make_float4(0.f, 0.f, 0.f, 0.f);
    if (lane < 8) r2 = __ldcs(v4 + lane + 64);

    const float qv = __ldcs(q + R * DD + lane);

    // ---- Stage lt[h] into shared once per block (all 8 rows share h: N % 8 == 0) ----
    const int hn0 = (int)(R0 % ((long long)HH * NN));  // h*N + n0
    const int h   = hn0 / NN;
    {
        const float* __restrict__ ltg = lt + h * (DD * KK);
        #pragma unroll
        for (int i = tid; i < DD * KK; i += WARPS_PER_BLOCK * 32)
            s_lt[i] = ltg[i];
    }
    __syncthreads();

    // ---- attn[k]: qv * lt[lane,k], butterfly-reduced over d ----
    float a[KK];
    #pragma unroll
    for (int k = 0; k < KK; k++) a[k] = qv * s_lt[lane * KK + k];

    #pragma unroll
    for (int off = 16; off > 0; off >>= 1) {
        #pragma unroll
        for (int k = 0; k < KK; k++)
            a[k] += __shfl_xor_sync(0xffffffffu, a[k], off);
    }

    // ---- bias[h,n,k] + local[b,h,n,k]: lanes 0-8 load, shuffle-broadcast ----
    const int hn = hn0 + warp;
    float bl = 0.f;
    if (lane < KK)
        bl = bias[(long long)hn * KK + lane] + __ldcs(attn_local + R * KK + lane);
    #pragma unroll
    for (int k = 0; k < KK; k++)
        a[k] += __shfl_sync(0xffffffffu, bl, k);

    // ---- Park v in shared, conflict-free scalar readback (gcd(9,32)=1) ----
    float4* s4 = reinterpret_cast<float4*>(sv[warp]);
    s4[lane]      = r0;
    s4[lane + 32] = r1;
    if (lane < 8) s4[lane + 64] = r2;
    __syncwarp();

    const float* __restrict__ srow = sv[warp] + lane * KK;
    float acc = 0.f;
    #pragma unroll
    for (int k = 0; k < KK; k++) acc = fmaf(a[k], srow[k], acc);

    out[R * DD + lane] = acc;
}

extern "C" void kernel_launch(void* const* d_in, const int* in_sizes, int n_in,
                              void* d_out, int out_size) {
    const float* q          = (const float*)d_in[0];  // [B,H,N,D]
    const float* attn_local = (const float*)d_in[1];  // [B,H,N,K2]
    const float* v_local    = (const float*)d_in[2];  // [B,H,N,D,K2]
    const float* lt         = (const float*)d_in[3];  // [H,D,K2]
    const float* bias       = (const float*)d_in[4];  // [H,N,K2]
    float* out = (float*)d_out;                       // [B,H,N,D]

    const int blocks = NROWS / ROWS_PER_BLOCK;        // 25088
    swattn_av_kernel<<<blocks, WARPS_PER_BLOCK * 32>>>(q, attn_local, v_local, lt, bias, out);
}

// round 3
// speedup vs baseline: 1.2345x; 1.1067x over previous
#include <cuda_runtime.h>

// SWAttention AV, two-phase block-cooperative version.
// B=8, H=8, N=3136, D=32, K2=9. Block = 288 threads (9 warps), 32 rows/block.
// Phase 1: attn[n,k] = q[n,:]·lt[:,k] + bias + local   (thread per (n,k), zero shuffles)
// Phase 2: out[n,d]  = sum_k attn[n,k]*v[n,d,k]        (warp per 4 rows, all LSU ops 128-bit)

#define HH 8
#define NN 3136
#define NROWS (8 * HH * NN)     // 200704
#define TILE 32
#define NBLOCKS (NROWS / TILE)  // 6272

__global__ __launch_bounds__(288, 3)
void swattn_kernel(const float* __restrict__ q,
                   const float* __restrict__ attn_local,
                   const float* __restrict__ v,
                   const float* __restrict__ lt,
                   const float* __restrict__ bias,
                   float* __restrict__ out) {
    __shared__ float sq[32 * 36];     // q tile, padded rows (144B, 16B-aligned, conflict-free f4)
    __shared__ float sltT[9 * 36];    // lt transposed [k][d], padded
    __shared__ float sa[32 * 12];     // attn tile, padded to 48B rows
    __shared__ float sv[8 * 1152];    // per-warp 4-row v buffers (warps 0-7)

    const int t    = threadIdx.x;
    const int w    = t >> 5;
    const int lane = t & 31;
    const int R0   = blockIdx.x * TILE;
    const int hn0  = R0 % (HH * NN);
    const int h    = hn0 / NN;

    // ---- Stage q tile (coalesced) ----
    for (int i = t; i < TILE * 32; i += 288)
        sq[(i >> 5) * 36 + (i & 31)] = __ldcs(q + (size_t)R0 * 32 + i);

    // ---- Stage lt transposed: sltT[k][d] = lt[h][d][k] ----
    {
        const int d = t / 9, k = t - 9 * d;       // t indexes source flat d*9+k
        sltT[k * 36 + d] = lt[h * 288 + t];
    }

    // ---- bias + local, perfectly coalesced (flat idx == t) ----
    const float bl = bias[(size_t)hn0 * 9 + t] + __ldcs(attn_local + (size_t)R0 * 9 + t);

    // ---- Issue v loads early (warps 0-7, 4 rows each, fully coalesced 128b) ----
    float4 vr[9];
    if (w < 8) {
        const float4* vg = reinterpret_cast<const float4*>(v + (size_t)(R0 + 4 * w) * 288);
        #pragma unroll
        for (int i = 0; i < 9; i++) vr[i] = __ldcs(vg + lane + 32 * i);
    }

    __syncthreads();

    // ---- Phase 1: attn (v loads in flight) ----
    {
        const int n = t / 9, k = t - 9 * n;
        const float4* q4 = reinterpret_cast<const float4*>(sq + n * 36);
        const float4* l4 = reinterpret_cast<const float4*>(sltT + k * 36);
        float acc = bl;
        #pragma unroll
        for (int i = 0; i < 8; i++) {
            float4 qa = q4[i], lb = l4[i];
            acc = fmaf(qa.x, lb.x, acc);
            acc = fmaf(qa.y, lb.y, acc);
            acc = fmaf(qa.z, lb.z, acc);
            acc = fmaf(qa.w, lb.w, acc);
        }
        sa[n * 12 + k] = acc;
    }

    // ---- Park v in shared (128b stores, conflict-free) ----
    if (w < 8) {
        float4* s4 = reinterpret_cast<float4*>(sv + w * 1152);
        #pragma unroll
        for (int i = 0; i < 9; i++) s4[lane + 32 * i] = vr[i];
    }

    __syncthreads();

    // ---- Phase 2: AV. Warp w -> rows 4w..4w+3. Lane: row = lane>>3, d-group = lane&7 ----
    if (w < 8) {
        const int row = lane >> 3;
        const int g7  = lane & 7;

        const float* sar = sa + (4 * w + row) * 12;
        const float4 A0 = reinterpret_cast<const float4*>(sar)[0];
        const float4 A1 = reinterpret_cast<const float4*>(sar)[1];
        const float a[9] = {A0.x, A0.y, A0.z, A0.w, A1.x, A1.y, A1.z, A1.w, sar[8]};

        // Lane's 36 contiguous floats = v[row][4*g7 .. 4*g7+3][0..8]; (d,k) decode is static.
        const float4* wv4 = reinterpret_cast<const float4*>(sv + w * 1152 + row * 288 + g7 * 36);
        float acc[4] = {0.f, 0.f, 0.f, 0.f};
        #pragma unroll
        for (int i = 0; i < 9; i++) {
            float4 wv = wv4[i];
            acc[(4 * i + 0) / 9] = fmaf(a[(4 * i + 0) % 9], wv.x, acc[(4 * i + 0) / 9]);
            acc[(4 * i + 1) / 9] = fmaf(a[(4 * i + 1) % 9], wv.y, acc[(4 * i + 1) / 9]);
            acc[(4 * i + 2) / 9] = fmaf(a[(4 * i + 2) % 9], wv.z, acc[(4 * i + 2) / 9]);
            acc[(4 * i + 3) / 9] = fmaf(a[(4 * i + 3) % 9], wv.w, acc[(4 * i + 3) / 9]);
        }

        float4 o = make_float4(acc[0], acc[1], acc[2], acc[3]);
        reinterpret_cast<float4*>(out + (size_t)(R0 + 4 * w + row) * 32 + 4 * g7)[0] = o;
    }
}

extern "C" void kernel_launch(void* const* d_in, const int* in_sizes, int n_in,
                              void* d_out, int out_size) {
    const float* q          = (const float*)d_in[0];  // [B,H,N,D]
    const float* attn_local = (const float*)d_in[1];  // [B,H,N,K2]
    const float* v_local    = (const float*)d_in[2];  // [B,H,N,D,K2]
    const float* lt         = (const float*)d_in[3];  // [H,D,K2]
    const float* bias       = (const float*)d_in[4];  // [H,N,K2]
    float* out = (float*)d_out;                       // [B,H,N,D]

    swattn_kernel<<<NBLOCKS, 288>>>(q, attn_local, v_local, lt, bias, out);
}

// round 4
// speedup vs baseline: 1.6481x; 1.3350x over previous
#include <cuda_runtime.h>

// SWAttention AV, two-phase block-cooperative, cp.async version.
// B=8, H=8, N=3136, D=32, K2=9. Block = 288 threads (9 warps), 32 rows/block.
// Phase 1: attn[n,k] = q[n,:]·lt[:,k] + bias + local   (thread per (n,k))
// Phase 2: out[n,d]  = sum_k attn[n,k]*v[n,d,k]        (warp per 4 rows, 128-bit LSU ops)
// v and q move global->shared via cp.async.cg (no register staging, no STS),
// dropping regs/thread so 5 CTAs/SM fit and the whole v tile stays in flight.

#define HH 8
#define NN 3136
#define NROWS (8 * HH * NN)     // 200704
#define TILE 32
#define NBLOCKS (NROWS / TILE)  // 6272

__device__ __forceinline__ unsigned smem_u32(const void* p) {
    return (unsigned)__cvta_generic_to_shared(p);
}
__device__ __forceinline__ void cp16(unsigned dst, const void* src) {
    asm volatile("cp.async.cg.shared.global [%0], [%1], 16;" :: "r"(dst), "l"(src));
}
__device__ __forceinline__ void cp_commit() {
    asm volatile("cp.async.commit_group;");
}

__global__ __launch_bounds__(288, 5)
void swattn_kernel(const float* __restrict__ q,
                   const float* __restrict__ attn_local,
                   const float* __restrict__ v,
                   const float* __restrict__ lt,
                   const float* __restrict__ bias,
                   float* __restrict__ out) {
    __shared__ float sq[32 * 36];     // q tile, padded rows (144B), conflict-free f4
    __shared__ float sltT[9 * 36];    // lt transposed [k][d], padded
    __shared__ float sa[32 * 12];     // attn tile
    __shared__ float sv[8 * 1152];    // per-warp 4-row v buffers (warps 0-7), 36864 B

    const int t    = threadIdx.x;
    const int w    = t >> 5;
    const int lane = t & 31;
    const int R0   = blockIdx.x * TILE;
    const int hn0  = R0 % (HH * NN);
    const int h    = hn0 / NN;

    // ---- Group A: q tile via cp.async (256 x 16B chunks) ----
    if (t < 256) {
        const int row  = t >> 3;
        const int col4 = (t & 7) << 2;
        cp16(smem_u32(sq + row * 36 + col4), q + (size_t)R0 * 32 + t * 4);
    }
    cp_commit();

    // ---- Group B: v tile via cp.async (warps 0-7, 9 x 16B chunks each thread) ----
    if (w < 8) {
        const float* vg = v + (size_t)(R0 + 4 * w) * 288;
        const unsigned sd = smem_u32(sv + w * 1152);
        #pragma unroll
        for (int i = 0; i < 9; i++)
            cp16(sd + (lane + 32 * i) * 16, vg + (lane + 32 * i) * 4);
    }
    cp_commit();

    // ---- lt transposed (tiny, regular ld/sts): sltT[k][d] = lt[h][d][k] ----
    {
        const int d = t / 9, k = t - 9 * d;
        sltT[k * 36 + d] = lt[h * 288 + t];
    }

    // ---- bias + local (coalesced, flat idx == t) ----
    const float bl = bias[(size_t)hn0 * 9 + t] + __ldcs(attn_local + (size_t)R0 * 9 + t);

    // ---- Wait for q (group A); v (group B) keeps streaming ----
    asm volatile("cp.async.wait_group 1;");
    __syncthreads();

    // ---- Phase 1: attn ----
    {
        const int n = t / 9, k = t - 9 * n;
        const float4* q4 = reinterpret_cast<const float4*>(sq + n * 36);
        const float4* l4 = reinterpret_cast<const float4*>(sltT + k * 36);
        float acc = bl;
        #pragma unroll
        for (int i = 0; i < 8; i++) {
            float4 qa = q4[i], lb = l4[i];
            acc = fmaf(qa.x, lb.x, acc);
            acc = fmaf(qa.y, lb.y, acc);
            acc = fmaf(qa.z, lb.z, acc);
            acc = fmaf(qa.w, lb.w, acc);
        }
        sa[n * 12 + k] = acc;
    }

    // ---- Wait for v ----
    asm volatile("cp.async.wait_group 0;");
    __syncthreads();

    // ---- Phase 2: AV. Warp w -> rows 4w..4w+3. Lane: row = lane>>3, d-group = lane&7 ----
    if (w < 8) {
        const int row = lane >> 3;
        const int g7  = lane & 7;

        const float* sar = sa + (4 * w + row) * 12;
        const float4 A0 = reinterpret_cast<const float4*>(sar)[0];
        const float4 A1 = reinterpret_cast<const float4*>(sar)[1];
        const float a[9] = {A0.x, A0.y, A0.z, A0.w, A1.x, A1.y, A1.z, A1.w, sar[8]};

        // Lane's 36 contiguous floats = v[row][4*g7 .. 4*g7+3][0..8]; (d,k) decode static.
        const float4* wv4 = reinterpret_cast<const float4*>(sv + w * 1152 + row * 288 + g7 * 36);
        float acc[4] = {0.f, 0.f, 0.f, 0.f};
        #pragma unroll
        for (int i = 0; i < 9; i++) {
            float4 wv = wv4[i];
            acc[(4 * i + 0) / 9] = fmaf(a[(4 * i + 0) % 9], wv.x, acc[(4 * i + 0) / 9]);
            acc[(4 * i + 1) / 9] = fmaf(a[(4 * i + 1) % 9], wv.y, acc[(4 * i + 1) / 9]);
            acc[(4 * i + 2) / 9] = fmaf(a[(4 * i + 2) % 9], wv.z, acc[(4 * i + 2) / 9]);
            acc[(4 * i + 3) / 9] = fmaf(a[(4 * i + 3) % 9], wv.w, acc[(4 * i + 3) / 9]);
        }

        float4 o = make_float4(acc[0], acc[1], acc[2], acc[3]);
        reinterpret_cast<float4*>(out + (size_t)(R0 + 4 * w + row) * 32 + 4 * g7)[0] = o;
    }
}

extern "C" void kernel_launch(void* const* d_in, const int* in_sizes, int n_in,
                              void* d_out, int out_size) {
    const float* q          = (const float*)d_in[0];  // [B,H,N,D]
    const float* attn_local = (const float*)d_in[1];  // [B,H,N,K2]
    const float* v_local    = (const float*)d_in[2];  // [B,H,N,D,K2]
    const float* lt         = (const float*)d_in[3];  // [H,D,K2]
    const float* bias       = (const float*)d_in[4];  // [H,N,K2]
    float* out = (float*)d_out;                       // [B,H,N,D]

    swattn_kernel<<<NBLOCKS, 288>>>(q, attn_local, v_local, lt, bias, out);
}